// round 15
// baseline (speedup 1.0000x reference)
#include <cuda_runtime.h>
#include <cuda_bf16.h>
#include <math.h>
#include <cstdint>

#define Bc 64
#define Tt 197
#define Dd 768
#define Hh 12
#define DKk 64
#define Mrows (Bc * Tt)   // 12608
#define NCH (Dd / 16)     // 48 K-chunks

typedef unsigned long long u64;

// ===== f32x2 helpers =====
__device__ __forceinline__ u64 pk2(float lo, float hi) {
    u64 r; asm("mov.b64 %0,{%1,%2};" : "=l"(r) : "f"(lo), "f"(hi)); return r;
}
__device__ __forceinline__ float2 upk2(u64 v) {
    float2 f; asm("mov.b64 {%0,%1},%2;" : "=f"(f.x), "=f"(f.y) : "l"(v)); return f;
}
__device__ __forceinline__ void ffma2(u64 &c, u64 a, u64 b) {
    asm("fma.rn.f32x2 %0,%1,%2,%0;" : "+l"(c) : "l"(a), "l"(b));
}

// ===== mma helpers =====
__device__ __forceinline__ uint32_t smem_u32(const void* p) {
    uint32_t a;
    asm("{ .reg .u64 t; cvta.to.shared.u64 t, %1; cvt.u32.u64 %0, t; }" : "=r"(a) : "l"(p));
    return a;
}
__device__ __forceinline__ void ldsm4(uint32_t* r, uint32_t addr) {
    asm volatile("ldmatrix.sync.aligned.m8n8.x4.shared.b16 {%0,%1,%2,%3}, [%4];"
                 : "=r"(r[0]), "=r"(r[1]), "=r"(r[2]), "=r"(r[3]) : "r"(addr));
}
__device__ __forceinline__ void mma16(float* d, const uint32_t* a, uint32_t b0, uint32_t b1) {
    asm volatile(
        "mma.sync.aligned.m16n8k16.row.col.f32.bf16.bf16.f32 "
        "{%0,%1,%2,%3},{%4,%5,%6,%7},{%8,%9},{%0,%1,%2,%3};"
        : "+f"(d[0]), "+f"(d[1]), "+f"(d[2]), "+f"(d[3])
        : "r"(a[0]), "r"(a[1]), "r"(a[2]), "r"(a[3]), "r"(b0), "r"(b1));
}

// ===== scratch =====
__device__ float g_q[Bc * Hh * Tt * DKk];
__device__ float g_k[Bc * Hh * Tt * DKk];
__device__ float g_v[Bc * Hh * Tt * DKk];
__device__ float g_ctx[Bc * Tt * Dd];

// ---------------------------------------------------------------------------
// FFMA2 GEMM (exact fp32) for Q/K — col-pair accumulators, A pre-duplicated
// in smem. Inner loop: 6 LDS.128 + 32 FFMA2, zero MOVs.
// As_dup: [2][KT][256] (row r dup at floats 2r,2r+1); Ws: [2][KT][128].
// ---------------------------------------------------------------------------
#define KT 16

__device__ __forceinline__ void gemm_core(
    const float* __restrict__ A, const float* __restrict__ W,
    const float* __restrict__ bias, float* __restrict__ out,
    float* Asd /*[2][KT*256]*/, float* Ws /*[2][KT*128]*/)
{
    const int tid = threadIdx.x;
    const int tx = tid & 15;
    const int ty = tid >> 4;
    const int m0 = blockIdx.y * 128;
    const int n0 = blockIdx.x * 128;

    // c2[i][j]: row i (i<4: ty*4+i; else 64+ty*4+i-4), col-pair j
    // (j<2: tx*4+2j; else 64+tx*4+2(j-2))
    u64 c2[8][4];
#pragma unroll
    for (int i = 0; i < 8; i++)
#pragma unroll
        for (int j = 0; j < 4; j++) c2[i][j] = 0ull;

    const int ar = tid >> 1;
    const int ah = tid & 1;
    const int wk = tid >> 5;
    const int wc = tid & 31;
    const bool arow_ok = (m0 + ar < Mrows);

    float4 a0, a1, w0, w1;

    // chunk 0: LDG + store into buf0
    {
        a0 = make_float4(0.f, 0.f, 0.f, 0.f); a1 = a0;
        if (arow_ok) {
            const float* Ap = A + (size_t)(m0 + ar) * Dd + ah * 8;
            a0 = *(const float4*)Ap;
            a1 = *(const float4*)(Ap + 4);
        }
        const float* Wp = W + (size_t)wk * Dd + n0 + wc * 4;
        w0 = *(const float4*)Wp;
        w1 = *(const float4*)(Wp + 8 * Dd);

        float* Ab = Asd;
        float* Wb = Ws;
        *(float2*)&Ab[(ah * 8 + 0) * 256 + ar * 2] = make_float2(a0.x, a0.x);
        *(float2*)&Ab[(ah * 8 + 1) * 256 + ar * 2] = make_float2(a0.y, a0.y);
        *(float2*)&Ab[(ah * 8 + 2) * 256 + ar * 2] = make_float2(a0.z, a0.z);
        *(float2*)&Ab[(ah * 8 + 3) * 256 + ar * 2] = make_float2(a0.w, a0.w);
        *(float2*)&Ab[(ah * 8 + 4) * 256 + ar * 2] = make_float2(a1.x, a1.x);
        *(float2*)&Ab[(ah * 8 + 5) * 256 + ar * 2] = make_float2(a1.y, a1.y);
        *(float2*)&Ab[(ah * 8 + 6) * 256 + ar * 2] = make_float2(a1.z, a1.z);
        *(float2*)&Ab[(ah * 8 + 7) * 256 + ar * 2] = make_float2(a1.w, a1.w);
        *(float4*)&Wb[wk * 128 + wc * 4]       = w0;
        *(float4*)&Wb[(wk + 8) * 128 + wc * 4] = w1;
    }
    __syncthreads();

    for (int c = 0; c < NCH; c++) {
        const int cur = c & 1;
        const bool has_next = (c + 1 < NCH);

        if (has_next) {   // LDG chunk c+1
            a0 = make_float4(0.f, 0.f, 0.f, 0.f); a1 = a0;
            if (arow_ok) {
                const float* Ap = A + (size_t)(m0 + ar) * Dd + (c + 1) * KT + ah * 8;
                a0 = *(const float4*)Ap;
                a1 = *(const float4*)(Ap + 4);
            }
            const float* Wp = W + (size_t)((c + 1) * KT + wk) * Dd + n0 + wc * 4;
            w0 = *(const float4*)Wp;
            w1 = *(const float4*)(Wp + 8 * Dd);
        }

        // compute on buf cur
        const float* Ab = Asd + cur * (KT * 256);
        const float* Wb = Ws + cur * (KT * 128);
#pragma unroll
        for (int kk = 0; kk < KT; kk++) {
            const float* Ak = Ab + kk * 256;
            const float* Wr = Wb + kk * 128;
            ulonglong2 aA = *(const ulonglong2*)&Ak[ty * 8];
            ulonglong2 aB = *(const ulonglong2*)&Ak[ty * 8 + 4];
            ulonglong2 aC = *(const ulonglong2*)&Ak[128 + ty * 8];
            ulonglong2 aD = *(const ulonglong2*)&Ak[128 + ty * 8 + 4];
            ulonglong2 b0 = *(const ulonglong2*)&Wr[tx * 4];
            ulonglong2 b1 = *(const ulonglong2*)&Wr[64 + tx * 4];
            u64 ap[8] = {aA.x, aA.y, aB.x, aB.y, aC.x, aC.y, aD.x, aD.y};
            u64 bp[4] = {b0.x, b0.y, b1.x, b1.y};
#pragma unroll
            for (int i = 0; i < 8; i++)
#pragma unroll
                for (int j = 0; j < 4; j++) ffma2(c2[i][j], ap[i], bp[j]);
        }

        if (has_next) {   // store chunk c+1 into other buffer
            float* Ab2 = Asd + (cur ^ 1) * (KT * 256);
            float* Wb2 = Ws + (cur ^ 1) * (KT * 128);
            *(float2*)&Ab2[(ah * 8 + 0) * 256 + ar * 2] = make_float2(a0.x, a0.x);
            *(float2*)&Ab2[(ah * 8 + 1) * 256 + ar * 2] = make_float2(a0.y, a0.y);
            *(float2*)&Ab2[(ah * 8 + 2) * 256 + ar * 2] = make_float2(a0.z, a0.z);
            *(float2*)&Ab2[(ah * 8 + 3) * 256 + ar * 2] = make_float2(a0.w, a0.w);
            *(float2*)&Ab2[(ah * 8 + 4) * 256 + ar * 2] = make_float2(a1.x, a1.x);
            *(float2*)&Ab2[(ah * 8 + 5) * 256 + ar * 2] = make_float2(a1.y, a1.y);
            *(float2*)&Ab2[(ah * 8 + 6) * 256 + ar * 2] = make_float2(a1.z, a1.z);
            *(float2*)&Ab2[(ah * 8 + 7) * 256 + ar * 2] = make_float2(a1.w, a1.w);
            *(float4*)&Wb2[wk * 128 + wc * 4]       = w0;
            *(float4*)&Wb2[(wk + 8) * 128 + wc * 4] = w1;
        }
        __syncthreads();
    }

    // epilogue: c2[i][j] = (out[r][cg], out[r][cg+1])
#pragma unroll
    for (int i = 0; i < 8; i++) {
        const int r = m0 + ((i < 4) ? (ty * 4 + i) : (64 + ty * 4 + (i - 4)));
        if (r >= Mrows) continue;
        const int bi = r / Tt, t = r - (r / Tt) * Tt;
#pragma unroll
        for (int j = 0; j < 4; j++) {
            const int cg = n0 + ((j < 2) ? (tx * 4 + 2 * j) : (64 + tx * 4 + 2 * (j - 2)));
            float2 f = upk2(c2[i][j]);
            f.x += bias[cg];
            f.y += bias[cg + 1];
            const int h = cg >> 6, dk = cg & 63;
            *(float2*)&out[(((size_t)(bi * Hh + h)) * Tt + t) * DKk + dk] = f;
        }
    }
}

__global__ void __launch_bounds__(256, 2) qk_kernel(
    const float* __restrict__ x,
    const float* __restrict__ Wq, const float* __restrict__ Wk2,
    const float* __restrict__ bq, const float* __restrict__ bk2,
    float* __restrict__ q, float* __restrict__ k)
{
    __shared__ float Asd[2 * KT * 256];   // 32 KB
    __shared__ float Ws[2 * KT * 128];    // 16 KB
    int z = blockIdx.z;
    gemm_core(x, z ? Wk2 : Wq, z ? bk2 : bq, z ? k : q, Asd, Ws);
}

// ---------------------------------------------------------------------------
// 2-limb 3-product BF16 GEMM (V, O) — double-buffered (R14, frozen).
// ---------------------------------------------------------------------------
#define RB 40
#define BUFB 20480u
#define GEMM_SMEM_BF (2 * 20480)

union Pack8 { __nv_bfloat16 b[8]; uint4 u; };

__device__ __forceinline__ void bf16_store_tile(
    __nv_bfloat16* smb, int buf, int tid, const float4* pa, const float* pw)
{
    __nv_bfloat16* As = smb + buf * (BUFB / 2);
    __nv_bfloat16* Ws = As + 128 * RB;
    {
        float vv[16];
#pragma unroll
        for (int i = 0; i < 4; i++) {
            vv[i * 4 + 0] = pa[i].x; vv[i * 4 + 1] = pa[i].y;
            vv[i * 4 + 2] = pa[i].z; vv[i * 4 + 3] = pa[i].w;
        }
        Pack8 h0, h1, m0p, m1p;
#pragma unroll
        for (int j = 0; j < 16; j++) {
            __nv_bfloat16 hb = __float2bfloat16_rn(vv[j]);
            __nv_bfloat16 mb = __float2bfloat16_rn(vv[j] - __bfloat162float(hb));
            if (j < 8) { h0.b[j] = hb; m0p.b[j] = mb; }
            else       { h1.b[j - 8] = hb; m1p.b[j - 8] = mb; }
        }
        __nv_bfloat16* Arow = As + tid * RB;
        *(uint4*)(Arow)      = h0.u;  *(uint4*)(Arow + 8)  = h1.u;
        *(uint4*)(Arow + 16) = m0p.u; *(uint4*)(Arow + 24) = m1p.u;
    }
    {
        Pack8 h0, h1, m0p, m1p;
#pragma unroll
        for (int j = 0; j < 16; j++) {
            __nv_bfloat16 hb = __float2bfloat16_rn(pw[j]);
            __nv_bfloat16 mb = __float2bfloat16_rn(pw[j] - __bfloat162float(hb));
            if (j < 8) { h0.b[j] = hb; m0p.b[j] = mb; }
            else       { h1.b[j - 8] = hb; m1p.b[j - 8] = mb; }
        }
        __nv_bfloat16* Wrow = Ws + tid * RB;
        *(uint4*)(Wrow)      = h0.u;  *(uint4*)(Wrow + 8)  = h1.u;
        *(uint4*)(Wrow + 16) = m0p.u; *(uint4*)(Wrow + 24) = m1p.u;
    }
}

__global__ void __launch_bounds__(128, 2) bf16_gemm_kernel(
    const float* __restrict__ A, const float* __restrict__ W,
    const float* __restrict__ bias, float* __restrict__ out, int mode)
{
    extern __shared__ __nv_bfloat16 smb[];
    const uint32_t base_u = smem_u32(smb);

    const int tid  = threadIdx.x;
    const int lane = tid & 31;
    const int wid  = tid >> 5;
    const int wm   = wid >> 1;
    const int wn   = wid & 1;
    const int m0   = blockIdx.y * 128;
    const int n0   = blockIdx.x * 128;
    const bool arow_ok = (m0 + tid < Mrows);

    float d[4][8][4];
#pragma unroll
    for (int mf = 0; mf < 4; mf++)
#pragma unroll
        for (int nf = 0; nf < 8; nf++)
#pragma unroll
            for (int i = 0; i < 4; i++) d[mf][nf][i] = 0.f;

    const uint32_t a_off = (uint32_t)(wm * 64 + (lane & 15)) * 80u + ((lane >> 4) << 4);
    const uint32_t b_off = 10240u + (uint32_t)(wn * 64 + ((lane >> 4) << 3) + (lane & 7)) * 80u
                         + (((lane >> 3) & 1) << 4);

    float4 pa[4];
    float  pw[16];

    {
        if (arow_ok) {
            const float* Ap = A + (size_t)(m0 + tid) * Dd;
#pragma unroll
            for (int i = 0; i < 4; i++) pa[i] = *(const float4*)(Ap + i * 4);
        } else {
#pragma unroll
            for (int i = 0; i < 4; i++) pa[i] = make_float4(0.f, 0.f, 0.f, 0.f);
        }
#pragma unroll
        for (int kq = 0; kq < 16; kq++)
            pw[kq] = W[(size_t)kq * Dd + n0 + tid];
        bf16_store_tile(smb, 0, tid, pa, pw);
    }
    __syncthreads();

    for (int c = 0; c < NCH; c++) {
        const int cur = c & 1;
        const bool has_next = (c + 1 < NCH);

        if (has_next) {
            if (arow_ok) {
                const float* Ap = A + (size_t)(m0 + tid) * Dd + (c + 1) * 16;
#pragma unroll
                for (int i = 0; i < 4; i++) pa[i] = *(const float4*)(Ap + i * 4);
            } else {
#pragma unroll
                for (int i = 0; i < 4; i++) pa[i] = make_float4(0.f, 0.f, 0.f, 0.f);
            }
#pragma unroll
            for (int kq = 0; kq < 16; kq++)
                pw[kq] = W[(size_t)((c + 1) * 16 + kq) * Dd + n0 + tid];
        }

        const uint32_t a_base = base_u + cur * BUFB + a_off;
        const uint32_t b_base = base_u + cur * BUFB + b_off;
        uint32_t ah[4][4], am[4][4], bh[4][4], bm[4][4];
#pragma unroll
        for (int mf = 0; mf < 4; mf++) ldsm4(ah[mf], a_base + mf * 1280u);
#pragma unroll
        for (int g = 0; g < 4; g++)    ldsm4(bh[g], b_base + g * 1280u);
#pragma unroll
        for (int mf = 0; mf < 4; mf++)
#pragma unroll
            for (int nf = 0; nf < 8; nf++)
                mma16(d[mf][nf], ah[mf], bh[nf >> 1][(nf & 1) * 2], bh[nf >> 1][(nf & 1) * 2 + 1]);
#pragma unroll
        for (int g = 0; g < 4; g++)    ldsm4(bm[g], b_base + g * 1280u + 32u);
#pragma unroll
        for (int mf = 0; mf < 4; mf++)
#pragma unroll
            for (int nf = 0; nf < 8; nf++)
                mma16(d[mf][nf], ah[mf], bm[nf >> 1][(nf & 1) * 2], bm[nf >> 1][(nf & 1) * 2 + 1]);
#pragma unroll
        for (int mf = 0; mf < 4; mf++) ldsm4(am[mf], a_base + mf * 1280u + 32u);
#pragma unroll
        for (int mf = 0; mf < 4; mf++)
#pragma unroll
            for (int nf = 0; nf < 8; nf++)
                mma16(d[mf][nf], am[mf], bh[nf >> 1][(nf & 1) * 2], bh[nf >> 1][(nf & 1) * 2 + 1]);

        if (has_next)
            bf16_store_tile(smb, cur ^ 1, tid, pa, pw);
        __syncthreads();
    }

    const int gid = lane >> 2, tig = lane & 3;
#pragma unroll
    for (int mf = 0; mf < 4; mf++) {
        const int r0 = m0 + wm * 64 + mf * 16 + gid;
        const int r1 = r0 + 8;
        int bi0 = 0, t0 = 0, bi1 = 0, t1 = 0;
        const bool v0 = (r0 < Mrows), v1 = (r1 < Mrows);
        if (v0) { bi0 = r0 / Tt; t0 = r0 - bi0 * Tt; }
        if (v1) { bi1 = r1 / Tt; t1 = r1 - bi1 * Tt; }
#pragma unroll
        for (int nf = 0; nf < 8; nf++) {
            const int cg = n0 + wn * 64 + nf * 8 + tig * 2;
            const float bx = bias[cg], by = bias[cg + 1];
            float2 o0 = make_float2(d[mf][nf][0] + bx, d[mf][nf][1] + by);
            float2 o1 = make_float2(d[mf][nf][2] + bx, d[mf][nf][3] + by);
            if (mode == 0) {
                const int h = cg >> 6, dk = cg & 63;
                if (v0) *(float2*)&out[(((size_t)(bi0 * Hh + h)) * Tt + t0) * DKk + dk] = o0;
                if (v1) *(float2*)&out[(((size_t)(bi1 * Hh + h)) * Tt + t1) * DKk + dk] = o1;
            } else {
                if (v0) *(float2*)&out[(size_t)r0 * Dd + cg] = o0;
                if (v1) *(float2*)&out[(size_t)r1 * Dd + cg] = o1;
            }
        }
    }
}

// ---------------------------------------------------------------------------
// Attention (frozen): per (b,h) CTA, 16 warps, 4 rows/warp, rotated smem.
// ---------------------------------------------------------------------------
#define NW 16
#define ATTN_SMEM ((2 * Tt * 64 + NW * 800) * 4)

__global__ void __launch_bounds__(32 * NW) attn3_kernel(
    const float* __restrict__ Q, const float* __restrict__ K,
    const float* __restrict__ V, float* __restrict__ ctx)
{
    extern __shared__ float sm[];
    float* Ks = sm;
    float* Vs = sm + Tt * 64;
    const int tid  = threadIdx.x;
    const int lane = tid & 31;
    const int w    = tid >> 5;
    float* Pg = sm + 2 * Tt * 64 + w * 800;

    const int bh = blockIdx.x;
    const int b  = bh / Hh;
    const int h  = bh - b * Hh;

    const float* Kb = K + (size_t)bh * Tt * DKk;
    const float* Vb = V + (size_t)bh * Tt * DKk;
    const float* Qb = Q + (size_t)bh * Tt * DKk;

    for (int e = tid; e < Tt * 32; e += 32 * NW) {
        int j = e >> 5, p = e & 31, c = 2 * p;
        int off = j * 64 + ((c + 2 * j) & 63);
        *(float2*)&Ks[off] = *(const float2*)&Kb[j * 64 + c];
        *(float2*)&Vs[off] = *(const float2*)&Vb[j * 64 + c];
    }
    __syncthreads();

    int jj[7], rot[7];
#pragma unroll
    for (int u = 0; u < 7; u++) {
        int j = lane + 32 * u;
        jj[u]  = (j > Tt - 1) ? (Tt - 1) : j;
        rot[u] = (2 * jj[u]) & 63;
    }
    const int myc = 2 * lane;

    for (int g = w; g < 50; g += NW) {
        const int r0 = g * 4;
        int rs[4];
#pragma unroll
        for (int s = 0; s < 4; s++) rs[s] = (r0 + s > Tt - 1) ? (Tt - 1) : (r0 + s);

        u64 acc[4][7];
#pragma unroll
        for (int s = 0; s < 4; s++)
#pragma unroll
            for (int u = 0; u < 7; u++) acc[s][u] = 0ull;

#pragma unroll
        for (int dc = 0; dc < 8; dc++) {
            u64 qp[4][4];
#pragma unroll
            for (int s = 0; s < 4; s++) {
                const float* qs = Qb + rs[s] * DKk + dc * 8;
                float4 qa = *(const float4*)qs;
                float4 qb = *(const float4*)(qs + 4);
                qp[s][0] = pk2(qa.x, qa.y); qp[s][1] = pk2(qa.z, qa.w);
                qp[s][2] = pk2(qb.x, qb.y); qp[s][3] = pk2(qb.z, qb.w);
            }
            const int c0 = dc * 8;
#pragma unroll
            for (int u = 0; u < 7; u++) {
                const float* kr = Ks + jj[u] * 64;
                u64 kp0 = *(const u64*)&kr[(c0 + 0 + rot[u]) & 63];
                u64 kp1 = *(const u64*)&kr[(c0 + 2 + rot[u]) & 63];
                u64 kp2 = *(const u64*)&kr[(c0 + 4 + rot[u]) & 63];
                u64 kp3 = *(const u64*)&kr[(c0 + 6 + rot[u]) & 63];
#pragma unroll
                for (int s = 0; s < 4; s++) {
                    ffma2(acc[s][u], qp[s][0], kp0);
                    ffma2(acc[s][u], qp[s][1], kp1);
                    ffma2(acc[s][u], qp[s][2], kp2);
                    ffma2(acc[s][u], qp[s][3], kp3);
                }
            }
        }

        float iv[4];
#pragma unroll
        for (int s = 0; s < 4; s++) {
            float sc[7];
            float mx = -1e30f;
#pragma unroll
            for (int u = 0; u < 7; u++) {
                float2 f = upk2(acc[s][u]);
                float val = floorf((f.x + f.y) * 0.125f);
                sc[u] = (lane + 32 * u < Tt) ? val : -1e30f;
                mx = fmaxf(mx, sc[u]);
            }
#pragma unroll
            for (int o = 16; o; o >>= 1) mx = fmaxf(mx, __shfl_xor_sync(0xffffffffu, mx, o));
            float sum = 0.f;
#pragma unroll
            for (int u = 0; u < 7; u++) {
                if (lane + 32 * u < Tt) {
                    float p = __expf(sc[u] - mx);
                    Pg[jj[u] * 4 + s] = p;
                    sum += p;
                }
            }
#pragma unroll
            for (int o = 16; o; o >>= 1) sum += __shfl_xor_sync(0xffffffffu, sum, o);
            iv[s] = 1.f / sum;
        }
        __syncwarp();

        u64 a[4] = {0ull, 0ull, 0ull, 0ull};
        for (int j = 0; j < Tt - 1; j += 2) {
            u64 v0 = *(const u64*)&Vs[j * 64 + ((myc + 2 * j) & 63)];
            u64 v1 = *(const u64*)&Vs[(j + 1) * 64 + ((myc + 2 * j + 2) & 63)];
            float4 pa = *(const float4*)&Pg[j * 4];
            float4 pb = *(const float4*)&Pg[j * 4 + 4];
            ffma2(a[0], pk2(pa.x, pa.x), v0); ffma2(a[0], pk2(pb.x, pb.x), v1);
            ffma2(a[1], pk2(pa.y, pa.y), v0); ffma2(a[1], pk2(pb.y, pb.y), v1);
            ffma2(a[2], pk2(pa.z, pa.z), v0); ffma2(a[2], pk2(pb.z, pb.z), v1);
            ffma2(a[3], pk2(pa.w, pa.w), v0); ffma2(a[3], pk2(pb.w, pb.w), v1);
        }
        {
            int j = Tt - 1;
            u64 v0 = *(const u64*)&Vs[j * 64 + ((myc + 2 * j) & 63)];
            float4 pa = *(const float4*)&Pg[j * 4];
            ffma2(a[0], pk2(pa.x, pa.x), v0);
            ffma2(a[1], pk2(pa.y, pa.y), v0);
            ffma2(a[2], pk2(pa.z, pa.z), v0);
            ffma2(a[3], pk2(pa.w, pa.w), v0);
        }

#pragma unroll
        for (int s = 0; s < 4; s++) {
            float2 o = upk2(a[s]);
            o.x *= iv[s]; o.y *= iv[s];
            *(float2*)&ctx[((size_t)(b * Tt + rs[s])) * Dd + h * DKk + myc] = o;
        }
        __syncwarp();
    }
}

// ---------------------------------------------------------------------------
extern "C" void kernel_launch(void* const* d_in, const int* in_sizes, int n_in,
                              void* d_out, int out_size)
{
    const float* x  = (const float*)d_in[0];
    const float* Wq = (const float*)d_in[1];
    const float* bq = (const float*)d_in[2];
    const float* Wk = (const float*)d_in[3];
    const float* bk = (const float*)d_in[4];
    const float* Wv = (const float*)d_in[5];
    const float* bv = (const float*)d_in[6];
    const float* Wo = (const float*)d_in[7];
    const float* bo = (const float*)d_in[8];
    float* out = (float*)d_out;

    float *q, *k, *v, *ctx;
    cudaGetSymbolAddress((void**)&q,   g_q);
    cudaGetSymbolAddress((void**)&k,   g_k);
    cudaGetSymbolAddress((void**)&v,   g_v);
    cudaGetSymbolAddress((void**)&ctx, g_ctx);

    cudaFuncSetAttribute(bf16_gemm_kernel,
                         cudaFuncAttributeMaxDynamicSharedMemorySize, GEMM_SMEM_BF);
    cudaFuncSetAttribute(attn3_kernel,
                         cudaFuncAttributeMaxDynamicSharedMemorySize, ATTN_SMEM);

    // Q, K: exact fp32 FFMA2 (floor-sensitive path)
    dim3 gqk(Dd / 128, (Mrows + 127) / 128, 2);   // 6 x 99 x 2
    qk_kernel<<<gqk, 256>>>(x, Wq, Wk, bq, bk, q, k);

    // V: bf16 2-limb 3-product (smooth path)
    dim3 gbf(Dd / 128, (Mrows + 127) / 128);      // 6 x 99
    bf16_gemm_kernel<<<gbf, 128, GEMM_SMEM_BF>>>(x, Wv, bv, v, 0);

    attn3_kernel<<<Bc * Hh, 32 * NW, ATTN_SMEM>>>(q, k, v, ctx);

    // O: bf16 2-limb 3-product
    bf16_gemm_kernel<<<gbf, 128, GEMM_SMEM_BF>>>(ctx, Wo, bo, out, 1);
}

// round 16
// speedup vs baseline: 1.0397x; 1.0397x over previous
#include <cuda_runtime.h>
#include <cuda_bf16.h>
#include <math.h>
#include <cstdint>

#define Bc 64
#define Tt 197
#define Dd 768
#define Hh 12
#define DKk 64
#define Mrows (Bc * Tt)   // 12608
#define NCH (Dd / 16)     // 48 K-chunks
#define PLANE (Mrows * Dd)

typedef unsigned long long u64;

// ===== f32x2 helpers =====
__device__ __forceinline__ u64 pk2(float lo, float hi) {
    u64 r; asm("mov.b64 %0,{%1,%2};" : "=l"(r) : "f"(lo), "f"(hi)); return r;
}
__device__ __forceinline__ float2 upk2(u64 v) {
    float2 f; asm("mov.b64 {%0,%1},%2;" : "=f"(f.x), "=f"(f.y) : "l"(v)); return f;
}
__device__ __forceinline__ void ffma2(u64 &c, u64 a, u64 b) {
    asm("fma.rn.f32x2 %0,%1,%2,%0;" : "+l"(c) : "l"(a), "l"(b));
}

// ===== mma helpers =====
__device__ __forceinline__ uint32_t smem_u32(const void* p) {
    uint32_t a;
    asm("{ .reg .u64 t; cvta.to.shared.u64 t, %1; cvt.u32.u64 %0, t; }" : "=r"(a) : "l"(p));
    return a;
}
__device__ __forceinline__ void ldsm4(uint32_t* r, uint32_t addr) {
    asm volatile("ldmatrix.sync.aligned.m8n8.x4.shared.b16 {%0,%1,%2,%3}, [%4];"
                 : "=r"(r[0]), "=r"(r[1]), "=r"(r[2]), "=r"(r[3]) : "r"(addr));
}
__device__ __forceinline__ void mma16(float* d, const uint32_t* a, uint32_t b0, uint32_t b1) {
    asm volatile(
        "mma.sync.aligned.m16n8k16.row.col.f32.bf16.bf16.f32 "
        "{%0,%1,%2,%3},{%4,%5,%6,%7},{%8,%9},{%0,%1,%2,%3};"
        : "+f"(d[0]), "+f"(d[1]), "+f"(d[2]), "+f"(d[3])
        : "r"(a[0]), "r"(a[1]), "r"(a[2]), "r"(a[3]), "r"(b0), "r"(b1));
}

// ===== scratch =====
__device__ float g_q[Bc * Hh * Tt * DKk];
__device__ float g_k[Bc * Hh * Tt * DKk];
__device__ float g_v[Bc * Hh * Tt * DKk];
__device__ __align__(16) __nv_bfloat16 g_xh[PLANE];
__device__ __align__(16) __nv_bfloat16 g_xm[PLANE];
__device__ __align__(16) __nv_bfloat16 g_ch[PLANE];
__device__ __align__(16) __nv_bfloat16 g_cm[PLANE];
__device__ __align__(16) __nv_bfloat16 g_wth[2 * Dd * Dd];   // [mat][n][k] hi
__device__ __align__(16) __nv_bfloat16 g_wtm[2 * Dd * Dd];   // [mat][n][k] lo

union Pack8 { __nv_bfloat16 b[8]; uint4 u; };

// ---------------------------------------------------------------------------
// split_x: fp32 plane -> bf16 h/m limb planes (streaming)
// ---------------------------------------------------------------------------
__global__ void split_x_kernel(const float* __restrict__ x,
                               __nv_bfloat16* __restrict__ xh,
                               __nv_bfloat16* __restrict__ xm)
{
    int i = blockIdx.x * 256 + threadIdx.x;   // group of 8 floats
    if (i >= PLANE / 8) return;
    float4 v0 = ((const float4*)x)[i * 2];
    float4 v1 = ((const float4*)x)[i * 2 + 1];
    float vv[8] = {v0.x, v0.y, v0.z, v0.w, v1.x, v1.y, v1.z, v1.w};
    Pack8 h, m;
#pragma unroll
    for (int j = 0; j < 8; j++) {
        __nv_bfloat16 hb = __float2bfloat16_rn(vv[j]);
        h.b[j] = hb;
        m.b[j] = __float2bfloat16_rn(vv[j] - __bfloat162float(hb));
    }
    ((uint4*)xh)[i] = h.u;
    ((uint4*)xm)[i] = m.u;
}

// ---------------------------------------------------------------------------
// split_w: Wv/Wo [k][n] fp32 -> transposed bf16 limb planes [n][k]
// ---------------------------------------------------------------------------
__global__ void split_w_kernel(const float* __restrict__ Wv,
                               const float* __restrict__ Wo,
                               __nv_bfloat16* __restrict__ wth,
                               __nv_bfloat16* __restrict__ wtm)
{
    __shared__ float ts[32][33];
    const int mat = blockIdx.z;
    const float* W = mat ? Wo : Wv;
    const int n0 = blockIdx.x * 32, k0 = blockIdx.y * 32;
    const int tx = threadIdx.x, ty = threadIdx.y;
#pragma unroll
    for (int p = 0; p < 4; p++)
        ts[ty + 8 * p][tx] = W[(size_t)(k0 + ty + 8 * p) * Dd + n0 + tx];
    __syncthreads();
#pragma unroll
    for (int p = 0; p < 4; p++) {
        int n = n0 + ty + 8 * p, k = k0 + tx;
        float v = ts[tx][ty + 8 * p];
        __nv_bfloat16 hb = __float2bfloat16_rn(v);
        __nv_bfloat16 mb = __float2bfloat16_rn(v - __bfloat162float(hb));
        size_t o = (size_t)mat * Dd * Dd + (size_t)n * Dd + k;
        wth[o] = hb;
        wtm[o] = mb;
    }
}

// ---------------------------------------------------------------------------
// FFMA2 GEMM (exact fp32) for Q/K — R14 proven double-buffered core.
// ---------------------------------------------------------------------------
#define KT 16

__device__ __forceinline__ void gemm_core(
    const float* __restrict__ A, const float* __restrict__ W,
    const float* __restrict__ bias, float* __restrict__ out,
    float* As, float* Ws)
{
    const int tid = threadIdx.x;
    const int tx = tid & 15;
    const int ty = tid >> 4;
    const int m0 = blockIdx.y * 128;
    const int n0 = blockIdx.x * 128;

    u64 c2[4][8];
#pragma unroll
    for (int i = 0; i < 4; i++)
#pragma unroll
        for (int j = 0; j < 8; j++) c2[i][j] = 0ull;

    const int ar = tid >> 1;
    const int ah = tid & 1;
    const int wk = tid >> 5;
    const int wc = tid & 31;
    const bool arow_ok = (m0 + ar < Mrows);

    float4 a0, a1, w0, w1;

    {
        a0 = make_float4(0.f, 0.f, 0.f, 0.f); a1 = a0;
        if (arow_ok) {
            const float* Ap = A + (size_t)(m0 + ar) * Dd + ah * 8;
            a0 = *(const float4*)Ap;
            a1 = *(const float4*)(Ap + 4);
        }
        const float* Wp = W + (size_t)wk * Dd + n0 + wc * 4;
        w0 = *(const float4*)Wp;
        w1 = *(const float4*)(Wp + 8 * Dd);

        As[(ah * 8 + 0) * 128 + ar] = a0.x; As[(ah * 8 + 1) * 128 + ar] = a0.y;
        As[(ah * 8 + 2) * 128 + ar] = a0.z; As[(ah * 8 + 3) * 128 + ar] = a0.w;
        As[(ah * 8 + 4) * 128 + ar] = a1.x; As[(ah * 8 + 5) * 128 + ar] = a1.y;
        As[(ah * 8 + 6) * 128 + ar] = a1.z; As[(ah * 8 + 7) * 128 + ar] = a1.w;
        *(float4*)&Ws[wk * 128 + wc * 4]       = w0;
        *(float4*)&Ws[(wk + 8) * 128 + wc * 4] = w1;
    }
    __syncthreads();

    for (int c = 0; c < NCH; c++) {
        const int cur = c & 1;
        const bool has_next = (c + 1 < NCH);

        if (has_next) {
            a0 = make_float4(0.f, 0.f, 0.f, 0.f); a1 = a0;
            if (arow_ok) {
                const float* Ap = A + (size_t)(m0 + ar) * Dd + (c + 1) * KT + ah * 8;
                a0 = *(const float4*)Ap;
                a1 = *(const float4*)(Ap + 4);
            }
            const float* Wp = W + (size_t)((c + 1) * KT + wk) * Dd + n0 + wc * 4;
            w0 = *(const float4*)Wp;
            w1 = *(const float4*)(Wp + 8 * Dd);
        }

        const float* Asb = As + cur * (KT * 128);
        const float* Wsb = Ws + cur * (KT * 128);
#pragma unroll
        for (int kk = 0; kk < KT; kk++) {
            const float* Ak = Asb + kk * 128;
            const float* Wr = Wsb + kk * 128;
            u64 ap[4];
            ap[0] = *(const u64*)&Ak[ty * 4];
            ap[1] = *(const u64*)&Ak[ty * 4 + 2];
            ap[2] = *(const u64*)&Ak[64 + ty * 4];
            ap[3] = *(const u64*)&Ak[64 + ty * 4 + 2];
            float4 bv0 = *(const float4*)&Wr[tx * 4];
            float4 bv1 = *(const float4*)&Wr[64 + tx * 4];
            u64 bd[8];
            bd[0] = pk2(bv0.x, bv0.x); bd[1] = pk2(bv0.y, bv0.y);
            bd[2] = pk2(bv0.z, bv0.z); bd[3] = pk2(bv0.w, bv0.w);
            bd[4] = pk2(bv1.x, bv1.x); bd[5] = pk2(bv1.y, bv1.y);
            bd[6] = pk2(bv1.z, bv1.z); bd[7] = pk2(bv1.w, bv1.w);
#pragma unroll
            for (int i = 0; i < 4; i++)
#pragma unroll
                for (int j = 0; j < 8; j++) ffma2(c2[i][j], ap[i], bd[j]);
        }

        if (has_next) {
            float* Asn = As + (cur ^ 1) * (KT * 128);
            float* Wsn = Ws + (cur ^ 1) * (KT * 128);
            Asn[(ah * 8 + 0) * 128 + ar] = a0.x; Asn[(ah * 8 + 1) * 128 + ar] = a0.y;
            Asn[(ah * 8 + 2) * 128 + ar] = a0.z; Asn[(ah * 8 + 3) * 128 + ar] = a0.w;
            Asn[(ah * 8 + 4) * 128 + ar] = a1.x; Asn[(ah * 8 + 5) * 128 + ar] = a1.y;
            Asn[(ah * 8 + 6) * 128 + ar] = a1.z; Asn[(ah * 8 + 7) * 128 + ar] = a1.w;
            *(float4*)&Wsn[wk * 128 + wc * 4]       = w0;
            *(float4*)&Wsn[(wk + 8) * 128 + wc * 4] = w1;
        }
        __syncthreads();
    }

#pragma unroll
    for (int i = 0; i < 4; i++) {
        int rbase = m0 + ((i < 2) ? (ty * 4 + i * 2) : (64 + ty * 4 + (i - 2) * 2));
#pragma unroll
        for (int j = 0; j < 8; j++) {
            int cidx = n0 + ((j < 4) ? (tx * 4 + j) : (64 + tx * 4 + (j - 4)));
            float2 f = upk2(c2[i][j]);
            float bia = bias[cidx];
            f.x += bia; f.y += bia;
#pragma unroll
            for (int s = 0; s < 2; s++) {
                int r = rbase + s;
                if (r >= Mrows) continue;
                float v = s ? f.y : f.x;
                int bi = r / Tt, t = r - (r / Tt) * Tt;
                int h = cidx >> 6, dk = cidx & 63;
                out[(((size_t)(bi * Hh + h)) * Tt + t) * DKk + dk] = v;
            }
        }
    }
}

__global__ void __launch_bounds__(256, 2) qk_kernel(
    const float* __restrict__ x,
    const float* __restrict__ Wq, const float* __restrict__ Wk2,
    const float* __restrict__ bq, const float* __restrict__ bk2,
    float* __restrict__ q, float* __restrict__ k)
{
    __shared__ float As[2 * KT * 128];
    __shared__ float Ws[2 * KT * 128];
    int z = blockIdx.z;
    gemm_core(x, z ? Wk2 : Wq, z ? bk2 : bq, z ? k : q, As, Ws);
}

// ---------------------------------------------------------------------------
// bf16 GEMM v3 (V, O): pre-split limb planes in, no converts in hot loop.
// CTA 128x128, 128 threads, warp tile 64x64, m16n8k16, 3 products, dbuf.
// ---------------------------------------------------------------------------
#define RB 40
#define BUFB 20480u
#define GEMM_SMEM_BF (2 * 20480)

__device__ __forceinline__ void store_tile3(
    __nv_bfloat16* smb, int buf, int tid, const uint4* av, const uint4* wv)
{
    __nv_bfloat16* As = smb + buf * (BUFB / 2);
    __nv_bfloat16* Ws = As + 128 * RB;
    __nv_bfloat16* Ar = As + tid * RB;
    *(uint4*)(Ar)      = av[0]; *(uint4*)(Ar + 8)  = av[1];
    *(uint4*)(Ar + 16) = av[2]; *(uint4*)(Ar + 24) = av[3];
    __nv_bfloat16* Wr = Ws + tid * RB;
    *(uint4*)(Wr)      = wv[0]; *(uint4*)(Wr + 8)  = wv[1];
    *(uint4*)(Wr + 16) = wv[2]; *(uint4*)(Wr + 24) = wv[3];
}

__global__ void __launch_bounds__(128, 2) bf16_gemm3_kernel(
    const __nv_bfloat16* __restrict__ Ah, const __nv_bfloat16* __restrict__ Am,
    const __nv_bfloat16* __restrict__ Wh, const __nv_bfloat16* __restrict__ Wm,
    const float* __restrict__ bias, float* __restrict__ out, int mode)
{
    extern __shared__ __nv_bfloat16 smb[];
    const uint32_t base_u = smem_u32(smb);

    const int tid  = threadIdx.x;
    const int lane = tid & 31;
    const int wid  = tid >> 5;
    const int wm   = wid >> 1;
    const int wn   = wid & 1;
    const int m0   = blockIdx.y * 128;
    const int n0   = blockIdx.x * 128;
    const bool arow_ok = (m0 + tid < Mrows);

    float d[4][8][4];
#pragma unroll
    for (int mf = 0; mf < 4; mf++)
#pragma unroll
        for (int nf = 0; nf < 8; nf++)
#pragma unroll
            for (int i = 0; i < 4; i++) d[mf][nf][i] = 0.f;

    const uint32_t a_off = (uint32_t)(wm * 64 + (lane & 15)) * 80u + ((lane >> 4) << 4);
    const uint32_t b_off = 10240u + (uint32_t)(wn * 64 + ((lane >> 4) << 3) + (lane & 7)) * 80u
                         + (((lane >> 3) & 1) << 4);

    uint4 av[4], wv[4];
    const uint4 z4 = make_uint4(0, 0, 0, 0);

    {   // chunk 0 LDG + store buf0
        if (arow_ok) {
            const __nv_bfloat16* Ap = Ah + (size_t)(m0 + tid) * Dd;
            const __nv_bfloat16* Mp = Am + (size_t)(m0 + tid) * Dd;
            av[0] = *(const uint4*)Ap; av[1] = *(const uint4*)(Ap + 8);
            av[2] = *(const uint4*)Mp; av[3] = *(const uint4*)(Mp + 8);
        } else { av[0] = av[1] = av[2] = av[3] = z4; }
        const __nv_bfloat16* Wp = Wh + (size_t)(n0 + tid) * Dd;
        const __nv_bfloat16* Vp = Wm + (size_t)(n0 + tid) * Dd;
        wv[0] = *(const uint4*)Wp; wv[1] = *(const uint4*)(Wp + 8);
        wv[2] = *(const uint4*)Vp; wv[3] = *(const uint4*)(Vp + 8);
        store_tile3(smb, 0, tid, av, wv);
    }
    __syncthreads();

    for (int c = 0; c < NCH; c++) {
        const int cur = c & 1;
        const bool has_next = (c + 1 < NCH);

        if (has_next) {
            if (arow_ok) {
                const __nv_bfloat16* Ap = Ah + (size_t)(m0 + tid) * Dd + (c + 1) * 16;
                const __nv_bfloat16* Mp = Am + (size_t)(m0 + tid) * Dd + (c + 1) * 16;
                av[0] = *(const uint4*)Ap; av[1] = *(const uint4*)(Ap + 8);
                av[2] = *(const uint4*)Mp; av[3] = *(const uint4*)(Mp + 8);
            } else { av[0] = av[1] = av[2] = av[3] = z4; }
            const __nv_bfloat16* Wp = Wh + (size_t)(n0 + tid) * Dd + (c + 1) * 16;
            const __nv_bfloat16* Vp = Wm + (size_t)(n0 + tid) * Dd + (c + 1) * 16;
            wv[0] = *(const uint4*)Wp; wv[1] = *(const uint4*)(Wp + 8);
            wv[2] = *(const uint4*)Vp; wv[3] = *(const uint4*)(Vp + 8);
        }

        const uint32_t a_base = base_u + cur * BUFB + a_off;
        const uint32_t b_base = base_u + cur * BUFB + b_off;
        uint32_t ah[4][4], am[4][4], bh[4][4], bm[4][4];
#pragma unroll
        for (int mf = 0; mf < 4; mf++) ldsm4(ah[mf], a_base + mf * 1280u);
#pragma unroll
        for (int g = 0; g < 4; g++)    ldsm4(bh[g], b_base + g * 1280u);
#pragma unroll
        for (int mf = 0; mf < 4; mf++)
#pragma unroll
            for (int nf = 0; nf < 8; nf++)
                mma16(d[mf][nf], ah[mf], bh[nf >> 1][(nf & 1) * 2], bh[nf >> 1][(nf & 1) * 2 + 1]);
#pragma unroll
        for (int g = 0; g < 4; g++)    ldsm4(bm[g], b_base + g * 1280u + 32u);
#pragma unroll
        for (int mf = 0; mf < 4; mf++)
#pragma unroll
            for (int nf = 0; nf < 8; nf++)
                mma16(d[mf][nf], ah[mf], bm[nf >> 1][(nf & 1) * 2], bm[nf >> 1][(nf & 1) * 2 + 1]);
#pragma unroll
        for (int mf = 0; mf < 4; mf++) ldsm4(am[mf], a_base + mf * 1280u + 32u);
#pragma unroll
        for (int mf = 0; mf < 4; mf++)
#pragma unroll
            for (int nf = 0; nf < 8; nf++)
                mma16(d[mf][nf], am[mf], bh[nf >> 1][(nf & 1) * 2], bh[nf >> 1][(nf & 1) * 2 + 1]);

        if (has_next)
            store_tile3(smb, cur ^ 1, tid, av, wv);
        __syncthreads();
    }

    const int gid = lane >> 2, tig = lane & 3;
#pragma unroll
    for (int mf = 0; mf < 4; mf++) {
        const int r0 = m0 + wm * 64 + mf * 16 + gid;
        const int r1 = r0 + 8;
        int bi0 = 0, t0 = 0, bi1 = 0, t1 = 0;
        const bool v0 = (r0 < Mrows), v1 = (r1 < Mrows);
        if (v0) { bi0 = r0 / Tt; t0 = r0 - bi0 * Tt; }
        if (v1) { bi1 = r1 / Tt; t1 = r1 - bi1 * Tt; }
#pragma unroll
        for (int nf = 0; nf < 8; nf++) {
            const int cg = n0 + wn * 64 + nf * 8 + tig * 2;
            const float bx = bias[cg], by = bias[cg + 1];
            float2 o0 = make_float2(d[mf][nf][0] + bx, d[mf][nf][1] + by);
            float2 o1 = make_float2(d[mf][nf][2] + bx, d[mf][nf][3] + by);
            if (mode == 0) {
                const int h = cg >> 6, dk = cg & 63;
                if (v0) *(float2*)&out[(((size_t)(bi0 * Hh + h)) * Tt + t0) * DKk + dk] = o0;
                if (v1) *(float2*)&out[(((size_t)(bi1 * Hh + h)) * Tt + t1) * DKk + dk] = o1;
            } else {
                if (v0) *(float2*)&out[(size_t)r0 * Dd + cg] = o0;
                if (v1) *(float2*)&out[(size_t)r1 * Dd + cg] = o1;
            }
        }
    }
}

// ---------------------------------------------------------------------------
// Attention: frozen core; epilogue writes ctx bf16 limb planes directly.
// ---------------------------------------------------------------------------
#define NW 16
#define ATTN_SMEM ((2 * Tt * 64 + NW * 800) * 4)

__global__ void __launch_bounds__(32 * NW) attn3_kernel(
    const float* __restrict__ Q, const float* __restrict__ K,
    const float* __restrict__ V,
    __nv_bfloat16* __restrict__ ch, __nv_bfloat16* __restrict__ cm)
{
    extern __shared__ float sm[];
    float* Ks = sm;
    float* Vs = sm + Tt * 64;
    const int tid  = threadIdx.x;
    const int lane = tid & 31;
    const int w    = tid >> 5;
    float* Pg = sm + 2 * Tt * 64 + w * 800;

    const int bh = blockIdx.x;
    const int b  = bh / Hh;
    const int h  = bh - b * Hh;

    const float* Kb = K + (size_t)bh * Tt * DKk;
    const float* Vb = V + (size_t)bh * Tt * DKk;
    const float* Qb = Q + (size_t)bh * Tt * DKk;

    for (int e = tid; e < Tt * 32; e += 32 * NW) {
        int j = e >> 5, p = e & 31, c = 2 * p;
        int off = j * 64 + ((c + 2 * j) & 63);
        *(float2*)&Ks[off] = *(const float2*)&Kb[j * 64 + c];
        *(float2*)&Vs[off] = *(const float2*)&Vb[j * 64 + c];
    }
    __syncthreads();

    int jj[7], rot[7];
#pragma unroll
    for (int u = 0; u < 7; u++) {
        int j = lane + 32 * u;
        jj[u]  = (j > Tt - 1) ? (Tt - 1) : j;
        rot[u] = (2 * jj[u]) & 63;
    }
    const int myc = 2 * lane;

    for (int g = w; g < 50; g += NW) {
        const int r0 = g * 4;
        int rs[4];
#pragma unroll
        for (int s = 0; s < 4; s++) rs[s] = (r0 + s > Tt - 1) ? (Tt - 1) : (r0 + s);

        u64 acc[4][7];
#pragma unroll
        for (int s = 0; s < 4; s++)
#pragma unroll
            for (int u = 0; u < 7; u++) acc[s][u] = 0ull;

#pragma unroll
        for (int dc = 0; dc < 8; dc++) {
            u64 qp[4][4];
#pragma unroll
            for (int s = 0; s < 4; s++) {
                const float* qs = Qb + rs[s] * DKk + dc * 8;
                float4 qa = *(const float4*)qs;
                float4 qb = *(const float4*)(qs + 4);
                qp[s][0] = pk2(qa.x, qa.y); qp[s][1] = pk2(qa.z, qa.w);
                qp[s][2] = pk2(qb.x, qb.y); qp[s][3] = pk2(qb.z, qb.w);
            }
            const int c0 = dc * 8;
#pragma unroll
            for (int u = 0; u < 7; u++) {
                const float* kr = Ks + jj[u] * 64;
                u64 kp0 = *(const u64*)&kr[(c0 + 0 + rot[u]) & 63];
                u64 kp1 = *(const u64*)&kr[(c0 + 2 + rot[u]) & 63];
                u64 kp2 = *(const u64*)&kr[(c0 + 4 + rot[u]) & 63];
                u64 kp3 = *(const u64*)&kr[(c0 + 6 + rot[u]) & 63];
#pragma unroll
                for (int s = 0; s < 4; s++) {
                    ffma2(acc[s][u], qp[s][0], kp0);
                    ffma2(acc[s][u], qp[s][1], kp1);
                    ffma2(acc[s][u], qp[s][2], kp2);
                    ffma2(acc[s][u], qp[s][3], kp3);
                }
            }
        }

        float iv[4];
#pragma unroll
        for (int s = 0; s < 4; s++) {
            float sc[7];
            float mx = -1e30f;
#pragma unroll
            for (int u = 0; u < 7; u++) {
                float2 f = upk2(acc[s][u]);
                float val = floorf((f.x + f.y) * 0.125f);
                sc[u] = (lane + 32 * u < Tt) ? val : -1e30f;
                mx = fmaxf(mx, sc[u]);
            }
#pragma unroll
            for (int o = 16; o; o >>= 1) mx = fmaxf(mx, __shfl_xor_sync(0xffffffffu, mx, o));
            float sum = 0.f;
#pragma unroll
            for (int u = 0; u < 7; u++) {
                if (lane + 32 * u < Tt) {
                    float p = __expf(sc[u] - mx);
                    Pg[jj[u] * 4 + s] = p;
                    sum += p;
                }
            }
#pragma unroll
            for (int o = 16; o; o >>= 1) sum += __shfl_xor_sync(0xffffffffu, sum, o);
            iv[s] = 1.f / sum;
        }
        __syncwarp();

        u64 a[4] = {0ull, 0ull, 0ull, 0ull};
        for (int j = 0; j < Tt - 1; j += 2) {
            u64 v0 = *(const u64*)&Vs[j * 64 + ((myc + 2 * j) & 63)];
            u64 v1 = *(const u64*)&Vs[(j + 1) * 64 + ((myc + 2 * j + 2) & 63)];
            float4 pa = *(const float4*)&Pg[j * 4];
            float4 pb = *(const float4*)&Pg[j * 4 + 4];
            ffma2(a[0], pk2(pa.x, pa.x), v0); ffma2(a[0], pk2(pb.x, pb.x), v1);
            ffma2(a[1], pk2(pa.y, pa.y), v0); ffma2(a[1], pk2(pb.y, pb.y), v1);
            ffma2(a[2], pk2(pa.z, pa.z), v0); ffma2(a[2], pk2(pb.z, pb.z), v1);
            ffma2(a[3], pk2(pa.w, pa.w), v0); ffma2(a[3], pk2(pb.w, pb.w), v1);
        }
        {
            int j = Tt - 1;
            u64 v0 = *(const u64*)&Vs[j * 64 + ((myc + 2 * j) & 63)];
            float4 pa = *(const float4*)&Pg[j * 4];
            ffma2(a[0], pk2(pa.x, pa.x), v0);
            ffma2(a[1], pk2(pa.y, pa.y), v0);
            ffma2(a[2], pk2(pa.z, pa.z), v0);
            ffma2(a[3], pk2(pa.w, pa.w), v0);
        }

#pragma unroll
        for (int s = 0; s < 4; s++) {
            float2 o = upk2(a[s]);
            o.x *= iv[s]; o.y *= iv[s];
            __nv_bfloat16 hx = __float2bfloat16_rn(o.x);
            __nv_bfloat16 hy = __float2bfloat16_rn(o.y);
            __nv_bfloat16 mxr = __float2bfloat16_rn(o.x - __bfloat162float(hx));
            __nv_bfloat16 myr = __float2bfloat16_rn(o.y - __bfloat162float(hy));
            size_t base = ((size_t)(b * Tt + rs[s])) * Dd + h * DKk + myc;
            *(__nv_bfloat162*)&ch[base] = __nv_bfloat162{hx, hy};
            *(__nv_bfloat162*)&cm[base] = __nv_bfloat162{mxr, myr};
        }
        __syncwarp();
    }
}

// ---------------------------------------------------------------------------
extern "C" void kernel_launch(void* const* d_in, const int* in_sizes, int n_in,
                              void* d_out, int out_size)
{
    const float* x  = (const float*)d_in[0];
    const float* Wq = (const float*)d_in[1];
    const float* bq = (const float*)d_in[2];
    const float* Wk = (const float*)d_in[3];
    const float* bk = (const float*)d_in[4];
    const float* Wv = (const float*)d_in[5];
    const float* bv = (const float*)d_in[6];
    const float* Wo = (const float*)d_in[7];
    const float* bo = (const float*)d_in[8];
    float* out = (float*)d_out;

    float *q, *k, *v;
    __nv_bfloat16 *xh, *xm, *ch, *cm, *wth, *wtm;
    cudaGetSymbolAddress((void**)&q,   g_q);
    cudaGetSymbolAddress((void**)&k,   g_k);
    cudaGetSymbolAddress((void**)&v,   g_v);
    cudaGetSymbolAddress((void**)&xh,  g_xh);
    cudaGetSymbolAddress((void**)&xm,  g_xm);
    cudaGetSymbolAddress((void**)&ch,  g_ch);
    cudaGetSymbolAddress((void**)&cm,  g_cm);
    cudaGetSymbolAddress((void**)&wth, g_wth);
    cudaGetSymbolAddress((void**)&wtm, g_wtm);

    cudaFuncSetAttribute(bf16_gemm3_kernel,
                         cudaFuncAttributeMaxDynamicSharedMemorySize, GEMM_SMEM_BF);
    cudaFuncSetAttribute(attn3_kernel,
                         cudaFuncAttributeMaxDynamicSharedMemorySize, ATTN_SMEM);

    // limb prep (tiny streaming kernels)
    split_x_kernel<<<(PLANE / 8 + 255) / 256, 256>>>(x, xh, xm);
    split_w_kernel<<<dim3(24, 24, 2), dim3(32, 8)>>>(Wv, Wo, wth, wtm);

    // Q, K: exact fp32 FFMA2 (floor-sensitive path)
    dim3 gqk(Dd / 128, (Mrows + 127) / 128, 2);   // 6 x 99 x 2
    qk_kernel<<<gqk, 256>>>(x, Wq, Wk, bq, bk, q, k);

    // V: bf16 limb-plane GEMM (smooth path)
    dim3 gbf(Dd / 128, (Mrows + 127) / 128);      // 6 x 99
    bf16_gemm3_kernel<<<gbf, 128, GEMM_SMEM_BF>>>(xh, xm, wth, wtm, bv, v, 0);

    // attention -> ctx limb planes
    attn3_kernel<<<Bc * Hh, 32 * NW, ATTN_SMEM>>>(q, k, v, ch, cm);

    // O: bf16 limb-plane GEMM
    bf16_gemm3_kernel<<<gbf, 128, GEMM_SMEM_BF>>>(ch, cm, wth + Dd * Dd, wtm + Dd * Dd,
                                                  bo, out, 1);
}

// round 17
// speedup vs baseline: 1.0874x; 1.0459x over previous
#include <cuda_runtime.h>
#include <cuda_bf16.h>
#include <math.h>
#include <cstdint>

#define Bc 64
#define Tt 197
#define Dd 768
#define Hh 12
#define DKk 64
#define Mrows (Bc * Tt)   // 12608
#define NCH (Dd / 16)     // 48 K-chunks
#define NMB 99            // m-blocks of 128
#define TILE_U4 640       // uint4 per 10240-byte tile

typedef unsigned long long u64;

// ===== f32x2 helpers =====
__device__ __forceinline__ u64 pk2(float lo, float hi) {
    u64 r; asm("mov.b64 %0,{%1,%2};" : "=l"(r) : "f"(lo), "f"(hi)); return r;
}
__device__ __forceinline__ float2 upk2(u64 v) {
    float2 f; asm("mov.b64 {%0,%1},%2;" : "=f"(f.x), "=f"(f.y) : "l"(v)); return f;
}
__device__ __forceinline__ void ffma2(u64 &c, u64 a, u64 b) {
    asm("fma.rn.f32x2 %0,%1,%2,%0;" : "+l"(c) : "l"(a), "l"(b));
}

// ===== mma / async helpers =====
__device__ __forceinline__ uint32_t smem_u32(const void* p) {
    uint32_t a;
    asm("{ .reg .u64 t; cvta.to.shared.u64 t, %1; cvt.u32.u64 %0, t; }" : "=r"(a) : "l"(p));
    return a;
}
__device__ __forceinline__ void ldsm4(uint32_t* r, uint32_t addr) {
    asm volatile("ldmatrix.sync.aligned.m8n8.x4.shared.b16 {%0,%1,%2,%3}, [%4];"
                 : "=r"(r[0]), "=r"(r[1]), "=r"(r[2]), "=r"(r[3]) : "r"(addr));
}
__device__ __forceinline__ void mma16(float* d, const uint32_t* a, uint32_t b0, uint32_t b1) {
    asm volatile(
        "mma.sync.aligned.m16n8k16.row.col.f32.bf16.bf16.f32 "
        "{%0,%1,%2,%3},{%4,%5,%6,%7},{%8,%9},{%0,%1,%2,%3};"
        : "+f"(d[0]), "+f"(d[1]), "+f"(d[2]), "+f"(d[3])
        : "r"(a[0]), "r"(a[1]), "r"(a[2]), "r"(a[3]), "r"(b0), "r"(b1));
}
#define CP_ASYNC16(sa, gp) \
    asm volatile("cp.async.cg.shared.global [%0], [%1], 16;" :: "r"(sa), "l"(gp) : "memory")
#define CP_COMMIT() asm volatile("cp.async.commit_group;" ::: "memory")
#define CP_WAIT0()  asm volatile("cp.async.wait_group 0;" ::: "memory")

// ===== scratch =====
__device__ float g_q[Bc * Hh * Tt * DKk];
__device__ float g_k[Bc * Hh * Tt * DKk];
__device__ float g_v[Bc * Hh * Tt * DKk];
__device__ __align__(16) uint4 g_at[NMB * NCH * TILE_U4];        // x limb tiles
__device__ __align__(16) uint4 g_ct[NMB * NCH * TILE_U4];        // ctx limb tiles
__device__ __align__(16) uint4 g_wt[2 * 6 * NCH * TILE_U4];      // Wv/Wo limb tiles

union Pack8 { __nv_bfloat16 b[8]; uint4 u; };

// ---------------------------------------------------------------------------
// prep_a: x fp32 -> A limb tiles (one tile per (mblock, chunk))
// tile layout: row r at bf16 offset r*40: [h0..h15 | m0..m15 | pad8]
// ---------------------------------------------------------------------------
__global__ void prep_a_kernel(const float* __restrict__ x, uint4* __restrict__ out)
{
    const int mb = blockIdx.x, c = blockIdx.y;
    const int r = threadIdx.x;
    const int gr = mb * 128 + r;
    float vv[16];
    if (gr < Mrows) {
        const float* p = x + (size_t)gr * Dd + c * 16;
#pragma unroll
        for (int i = 0; i < 4; i++) {
            float4 v = *(const float4*)(p + i * 4);
            vv[i * 4 + 0] = v.x; vv[i * 4 + 1] = v.y; vv[i * 4 + 2] = v.z; vv[i * 4 + 3] = v.w;
        }
    } else {
#pragma unroll
        for (int i = 0; i < 16; i++) vv[i] = 0.f;
    }
    Pack8 h0, h1, m0, m1;
#pragma unroll
    for (int j = 0; j < 16; j++) {
        __nv_bfloat16 hb = __float2bfloat16_rn(vv[j]);
        __nv_bfloat16 mb2 = __float2bfloat16_rn(vv[j] - __bfloat162float(hb));
        if (j < 8) { h0.b[j] = hb; m0.b[j] = mb2; }
        else       { h1.b[j - 8] = hb; m1.b[j - 8] = mb2; }
    }
    __nv_bfloat16* t = (__nv_bfloat16*)(out + ((size_t)mb * NCH + c) * TILE_U4) + r * 40;
    *(uint4*)(t)      = h0.u; *(uint4*)(t + 8)  = h1.u;
    *(uint4*)(t + 16) = m0.u; *(uint4*)(t + 24) = m1.u;
}

// ---------------------------------------------------------------------------
// prep_w: Wv/Wo [k][n] fp32 -> W limb tiles [mat][nblock][chunk]
// thread tid owns n-column n0+tid; reads are lane-coalesced.
// ---------------------------------------------------------------------------
__global__ void prep_w_kernel(const float* __restrict__ Wv, const float* __restrict__ Wo,
                              uint4* __restrict__ out)
{
    const int nb = blockIdx.x, c = blockIdx.y, mat = blockIdx.z;
    const float* W = mat ? Wo : Wv;
    const int tid = threadIdx.x;
    float vv[16];
#pragma unroll
    for (int kq = 0; kq < 16; kq++)
        vv[kq] = W[(size_t)(c * 16 + kq) * Dd + nb * 128 + tid];
    Pack8 h0, h1, m0, m1;
#pragma unroll
    for (int j = 0; j < 16; j++) {
        __nv_bfloat16 hb = __float2bfloat16_rn(vv[j]);
        __nv_bfloat16 mb2 = __float2bfloat16_rn(vv[j] - __bfloat162float(hb));
        if (j < 8) { h0.b[j] = hb; m0.b[j] = mb2; }
        else       { h1.b[j - 8] = hb; m1.b[j - 8] = mb2; }
    }
    __nv_bfloat16* t = (__nv_bfloat16*)(out + (((size_t)mat * 6 + nb) * NCH + c) * TILE_U4) + tid * 40;
    *(uint4*)(t)      = h0.u; *(uint4*)(t + 8)  = h1.u;
    *(uint4*)(t + 16) = m0.u; *(uint4*)(t + 24) = m1.u;
}

// ---------------------------------------------------------------------------
// FFMA2 GEMM (exact fp32) for Q/K — R14 proven double-buffered core.
// ---------------------------------------------------------------------------
#define KT 16

__device__ __forceinline__ void gemm_core(
    const float* __restrict__ A, const float* __restrict__ W,
    const float* __restrict__ bias, float* __restrict__ out,
    float* As, float* Ws)
{
    const int tid = threadIdx.x;
    const int tx = tid & 15;
    const int ty = tid >> 4;
    const int m0 = blockIdx.y * 128;
    const int n0 = blockIdx.x * 128;

    u64 c2[4][8];
#pragma unroll
    for (int i = 0; i < 4; i++)
#pragma unroll
        for (int j = 0; j < 8; j++) c2[i][j] = 0ull;

    const int ar = tid >> 1;
    const int ah = tid & 1;
    const int wk = tid >> 5;
    const int wc = tid & 31;
    const bool arow_ok = (m0 + ar < Mrows);

    float4 a0, a1, w0, w1;
    {
        a0 = make_float4(0.f, 0.f, 0.f, 0.f); a1 = a0;
        if (arow_ok) {
            const float* Ap = A + (size_t)(m0 + ar) * Dd + ah * 8;
            a0 = *(const float4*)Ap;
            a1 = *(const float4*)(Ap + 4);
        }
        const float* Wp = W + (size_t)wk * Dd + n0 + wc * 4;
        w0 = *(const float4*)Wp;
        w1 = *(const float4*)(Wp + 8 * Dd);

        As[(ah * 8 + 0) * 128 + ar] = a0.x; As[(ah * 8 + 1) * 128 + ar] = a0.y;
        As[(ah * 8 + 2) * 128 + ar] = a0.z; As[(ah * 8 + 3) * 128 + ar] = a0.w;
        As[(ah * 8 + 4) * 128 + ar] = a1.x; As[(ah * 8 + 5) * 128 + ar] = a1.y;
        As[(ah * 8 + 6) * 128 + ar] = a1.z; As[(ah * 8 + 7) * 128 + ar] = a1.w;
        *(float4*)&Ws[wk * 128 + wc * 4]       = w0;
        *(float4*)&Ws[(wk + 8) * 128 + wc * 4] = w1;
    }
    __syncthreads();

    for (int c = 0; c < NCH; c++) {
        const int cur = c & 1;
        const bool has_next = (c + 1 < NCH);

        if (has_next) {
            a0 = make_float4(0.f, 0.f, 0.f, 0.f); a1 = a0;
            if (arow_ok) {
                const float* Ap = A + (size_t)(m0 + ar) * Dd + (c + 1) * KT + ah * 8;
                a0 = *(const float4*)Ap;
                a1 = *(const float4*)(Ap + 4);
            }
            const float* Wp = W + (size_t)((c + 1) * KT + wk) * Dd + n0 + wc * 4;
            w0 = *(const float4*)Wp;
            w1 = *(const float4*)(Wp + 8 * Dd);
        }

        const float* Asb = As + cur * (KT * 128);
        const float* Wsb = Ws + cur * (KT * 128);
#pragma unroll
        for (int kk = 0; kk < KT; kk++) {
            const float* Ak = Asb + kk * 128;
            const float* Wr = Wsb + kk * 128;
            u64 ap[4];
            ap[0] = *(const u64*)&Ak[ty * 4];
            ap[1] = *(const u64*)&Ak[ty * 4 + 2];
            ap[2] = *(const u64*)&Ak[64 + ty * 4];
            ap[3] = *(const u64*)&Ak[64 + ty * 4 + 2];
            float4 bv0 = *(const float4*)&Wr[tx * 4];
            float4 bv1 = *(const float4*)&Wr[64 + tx * 4];
            u64 bd[8];
            bd[0] = pk2(bv0.x, bv0.x); bd[1] = pk2(bv0.y, bv0.y);
            bd[2] = pk2(bv0.z, bv0.z); bd[3] = pk2(bv0.w, bv0.w);
            bd[4] = pk2(bv1.x, bv1.x); bd[5] = pk2(bv1.y, bv1.y);
            bd[6] = pk2(bv1.z, bv1.z); bd[7] = pk2(bv1.w, bv1.w);
#pragma unroll
            for (int i = 0; i < 4; i++)
#pragma unroll
                for (int j = 0; j < 8; j++) ffma2(c2[i][j], ap[i], bd[j]);
        }

        if (has_next) {
            float* Asn = As + (cur ^ 1) * (KT * 128);
            float* Wsn = Ws + (cur ^ 1) * (KT * 128);
            Asn[(ah * 8 + 0) * 128 + ar] = a0.x; Asn[(ah * 8 + 1) * 128 + ar] = a0.y;
            Asn[(ah * 8 + 2) * 128 + ar] = a0.z; Asn[(ah * 8 + 3) * 128 + ar] = a0.w;
            Asn[(ah * 8 + 4) * 128 + ar] = a1.x; Asn[(ah * 8 + 5) * 128 + ar] = a1.y;
            Asn[(ah * 8 + 6) * 128 + ar] = a1.z; Asn[(ah * 8 + 7) * 128 + ar] = a1.w;
            *(float4*)&Wsn[wk * 128 + wc * 4]       = w0;
            *(float4*)&Wsn[(wk + 8) * 128 + wc * 4] = w1;
        }
        __syncthreads();
    }

#pragma unroll
    for (int i = 0; i < 4; i++) {
        int rbase = m0 + ((i < 2) ? (ty * 4 + i * 2) : (64 + ty * 4 + (i - 2) * 2));
#pragma unroll
        for (int j = 0; j < 8; j++) {
            int cidx = n0 + ((j < 4) ? (tx * 4 + j) : (64 + tx * 4 + (j - 4)));
            float2 f = upk2(c2[i][j]);
            float bia = bias[cidx];
            f.x += bia; f.y += bia;
#pragma unroll
            for (int s = 0; s < 2; s++) {
                int r = rbase + s;
                if (r >= Mrows) continue;
                float v = s ? f.y : f.x;
                int bi = r / Tt, t = r - (r / Tt) * Tt;
                int h = cidx >> 6, dk = cidx & 63;
                out[(((size_t)(bi * Hh + h)) * Tt + t) * DKk + dk] = v;
            }
        }
    }
}

__global__ void __launch_bounds__(256, 2) qk_kernel(
    const float* __restrict__ x,
    const float* __restrict__ Wq, const float* __restrict__ Wk2,
    const float* __restrict__ bq, const float* __restrict__ bk2,
    float* __restrict__ q, float* __restrict__ k)
{
    __shared__ float As[2 * KT * 128];
    __shared__ float Ws[2 * KT * 128];
    int z = blockIdx.z;
    gemm_core(x, z ? Wk2 : Wq, z ? bk2 : bq, z ? k : q, As, Ws);
}

// ---------------------------------------------------------------------------
// bf16 GEMM v4 (V, O): pre-tiled limb buffers, cp.async identity copy.
// CTA 128x128, 128 threads, warp tile 64x64, m16n8k16, 3 products.
// ---------------------------------------------------------------------------
#define BUFB 20480u
#define GEMM_SMEM_BF (2 * 20480)

__device__ __forceinline__ void issue_copy(uint32_t sbuf, const uint4* Asrc,
                                           const uint4* Wsrc, int tid)
{
#pragma unroll
    for (int i = 0; i < 5; i++) {
        CP_ASYNC16(sbuf + (uint32_t)(i * 128 + tid) * 16u, Asrc + i * 128 + tid);
        CP_ASYNC16(sbuf + 10240u + (uint32_t)(i * 128 + tid) * 16u, Wsrc + i * 128 + tid);
    }
}

__global__ void __launch_bounds__(128, 2) bf16_gemm4_kernel(
    const uint4* __restrict__ At, const uint4* __restrict__ Wt,
    const float* __restrict__ bias, float* __restrict__ out, int mode)
{
    extern __shared__ __nv_bfloat16 smb[];
    const uint32_t base_u = smem_u32(smb);

    const int tid  = threadIdx.x;
    const int lane = tid & 31;
    const int wid  = tid >> 5;
    const int wm   = wid >> 1;
    const int wn   = wid & 1;
    const int mb   = blockIdx.y;
    const int nb   = blockIdx.x;
    const int m0   = mb * 128;
    const int n0   = nb * 128;

    float d[4][8][4];
#pragma unroll
    for (int mf = 0; mf < 4; mf++)
#pragma unroll
        for (int nf = 0; nf < 8; nf++)
#pragma unroll
            for (int i = 0; i < 4; i++) d[mf][nf][i] = 0.f;

    const uint32_t a_off = (uint32_t)(wm * 64 + (lane & 15)) * 80u + ((lane >> 4) << 4);
    const uint32_t b_off = 10240u + (uint32_t)(wn * 64 + ((lane >> 4) << 3) + (lane & 7)) * 80u
                         + (((lane >> 3) & 1) << 4);

    const uint4* Atile = At + (size_t)mb * NCH * TILE_U4;
    const uint4* Wtile = Wt + (size_t)nb * NCH * TILE_U4;

    issue_copy(base_u, Atile, Wtile, tid);
    CP_COMMIT();

    for (int c = 0; c < NCH; c++) {
        const int cur = c & 1;
        CP_WAIT0();
        __syncthreads();
        if (c + 1 < NCH) {
            issue_copy(base_u + (uint32_t)((c + 1) & 1) * BUFB,
                       Atile + (c + 1) * TILE_U4, Wtile + (c + 1) * TILE_U4, tid);
            CP_COMMIT();
        }

        const uint32_t a_base = base_u + cur * BUFB + a_off;
        const uint32_t b_base = base_u + cur * BUFB + b_off;
        uint32_t ah[4][4], am[4][4], bh[4][4], bm[4][4];
#pragma unroll
        for (int mf = 0; mf < 4; mf++) ldsm4(ah[mf], a_base + mf * 1280u);
#pragma unroll
        for (int g = 0; g < 4; g++)    ldsm4(bh[g], b_base + g * 1280u);
#pragma unroll
        for (int mf = 0; mf < 4; mf++)
#pragma unroll
            for (int nf = 0; nf < 8; nf++)
                mma16(d[mf][nf], ah[mf], bh[nf >> 1][(nf & 1) * 2], bh[nf >> 1][(nf & 1) * 2 + 1]);
#pragma unroll
        for (int g = 0; g < 4; g++)    ldsm4(bm[g], b_base + g * 1280u + 32u);
#pragma unroll
        for (int mf = 0; mf < 4; mf++)
#pragma unroll
            for (int nf = 0; nf < 8; nf++)
                mma16(d[mf][nf], ah[mf], bm[nf >> 1][(nf & 1) * 2], bm[nf >> 1][(nf & 1) * 2 + 1]);
#pragma unroll
        for (int mf = 0; mf < 4; mf++) ldsm4(am[mf], a_base + mf * 1280u + 32u);
#pragma unroll
        for (int mf = 0; mf < 4; mf++)
#pragma unroll
            for (int nf = 0; nf < 8; nf++)
                mma16(d[mf][nf], am[mf], bh[nf >> 1][(nf & 1) * 2], bh[nf >> 1][(nf & 1) * 2 + 1]);
    }

    const int gid = lane >> 2, tig = lane & 3;
#pragma unroll
    for (int mf = 0; mf < 4; mf++) {
        const int r0 = m0 + wm * 64 + mf * 16 + gid;
        const int r1 = r0 + 8;
        int bi0 = 0, t0 = 0, bi1 = 0, t1 = 0;
        const bool v0 = (r0 < Mrows), v1 = (r1 < Mrows);
        if (v0) { bi0 = r0 / Tt; t0 = r0 - bi0 * Tt; }
        if (v1) { bi1 = r1 / Tt; t1 = r1 - bi1 * Tt; }
#pragma unroll
        for (int nf = 0; nf < 8; nf++) {
            const int cg = n0 + wn * 64 + nf * 8 + tig * 2;
            const float bx = bias[cg], by = bias[cg + 1];
            float2 o0 = make_float2(d[mf][nf][0] + bx, d[mf][nf][1] + by);
            float2 o1 = make_float2(d[mf][nf][2] + bx, d[mf][nf][3] + by);
            if (mode == 0) {
                const int h = cg >> 6, dk = cg & 63;
                if (v0) *(float2*)&out[(((size_t)(bi0 * Hh + h)) * Tt + t0) * DKk + dk] = o0;
                if (v1) *(float2*)&out[(((size_t)(bi1 * Hh + h)) * Tt + t1) * DKk + dk] = o1;
            } else {
                if (v0) *(float2*)&out[(size_t)r0 * Dd + cg] = o0;
                if (v1) *(float2*)&out[(size_t)r1 * Dd + cg] = o1;
            }
        }
    }
}

// ---------------------------------------------------------------------------
// Attention: frozen core; epilogue writes ctx limbs directly into tile layout.
// ---------------------------------------------------------------------------
#define NW 16
#define ATTN_SMEM ((2 * Tt * 64 + NW * 800) * 4)

__global__ void __launch_bounds__(32 * NW) attn3_kernel(
    const float* __restrict__ Q, const float* __restrict__ K,
    const float* __restrict__ V, uint4* __restrict__ ct)
{
    extern __shared__ float sm[];
    float* Ks = sm;
    float* Vs = sm + Tt * 64;
    const int tid  = threadIdx.x;
    const int lane = tid & 31;
    const int w    = tid >> 5;
    float* Pg = sm + 2 * Tt * 64 + w * 800;

    const int bh = blockIdx.x;
    const int b  = bh / Hh;
    const int h  = bh - b * Hh;

    const float* Kb = K + (size_t)bh * Tt * DKk;
    const float* Vb = V + (size_t)bh * Tt * DKk;
    const float* Qb = Q + (size_t)bh * Tt * DKk;

    for (int e = tid; e < Tt * 32; e += 32 * NW) {
        int j = e >> 5, p = e & 31, c = 2 * p;
        int off = j * 64 + ((c + 2 * j) & 63);
        *(float2*)&Ks[off] = *(const float2*)&Kb[j * 64 + c];
        *(float2*)&Vs[off] = *(const float2*)&Vb[j * 64 + c];
    }
    __syncthreads();

    int jj[7], rot[7];
#pragma unroll
    for (int u = 0; u < 7; u++) {
        int j = lane + 32 * u;
        jj[u]  = (j > Tt - 1) ? (Tt - 1) : j;
        rot[u] = (2 * jj[u]) & 63;
    }
    const int myc = 2 * lane;
    // ctx tile coordinates for this (h, myc)
    const int kb   = h * DKk + myc;
    const int chk  = kb >> 4;
    const int koff = kb & 15;

    for (int g = w; g < 50; g += NW) {
        const int r0 = g * 4;
        int rs[4];
#pragma unroll
        for (int s = 0; s < 4; s++) rs[s] = (r0 + s > Tt - 1) ? (Tt - 1) : (r0 + s);

        u64 acc[4][7];
#pragma unroll
        for (int s = 0; s < 4; s++)
#pragma unroll
            for (int u = 0; u < 7; u++) acc[s][u] = 0ull;

#pragma unroll
        for (int dc = 0; dc < 8; dc++) {
            u64 qp[4][4];
#pragma unroll
            for (int s = 0; s < 4; s++) {
                const float* qs = Qb + rs[s] * DKk + dc * 8;
                float4 qa = *(const float4*)qs;
                float4 qb = *(const float4*)(qs + 4);
                qp[s][0] = pk2(qa.x, qa.y); qp[s][1] = pk2(qa.z, qa.w);
                qp[s][2] = pk2(qb.x, qb.y); qp[s][3] = pk2(qb.z, qb.w);
            }
            const int c0 = dc * 8;
#pragma unroll
            for (int u = 0; u < 7; u++) {
                const float* kr = Ks + jj[u] * 64;
                u64 kp0 = *(const u64*)&kr[(c0 + 0 + rot[u]) & 63];
                u64 kp1 = *(const u64*)&kr[(c0 + 2 + rot[u]) & 63];
                u64 kp2 = *(const u64*)&kr[(c0 + 4 + rot[u]) & 63];
                u64 kp3 = *(const u64*)&kr[(c0 + 6 + rot[u]) & 63];
#pragma unroll
                for (int s = 0; s < 4; s++) {
                    ffma2(acc[s][u], qp[s][0], kp0);
                    ffma2(acc[s][u], qp[s][1], kp1);
                    ffma2(acc[s][u], qp[s][2], kp2);
                    ffma2(acc[s][u], qp[s][3], kp3);
                }
            }
        }

        float iv[4];
#pragma unroll
        for (int s = 0; s < 4; s++) {
            float sc[7];
            float mx = -1e30f;
#pragma unroll
            for (int u = 0; u < 7; u++) {
                float2 f = upk2(acc[s][u]);
                float val = floorf((f.x + f.y) * 0.125f);
                sc[u] = (lane + 32 * u < Tt) ? val : -1e30f;
                mx = fmaxf(mx, sc[u]);
            }
#pragma unroll
            for (int o = 16; o; o >>= 1) mx = fmaxf(mx, __shfl_xor_sync(0xffffffffu, mx, o));
            float sum = 0.f;
#pragma unroll
            for (int u = 0; u < 7; u++) {
                if (lane + 32 * u < Tt) {
                    float p = __expf(sc[u] - mx);
                    Pg[jj[u] * 4 + s] = p;
                    sum += p;
                }
            }
#pragma unroll
            for (int o = 16; o; o >>= 1) sum += __shfl_xor_sync(0xffffffffu, sum, o);
            iv[s] = 1.f / sum;
        }
        __syncwarp();

        u64 a[4] = {0ull, 0ull, 0ull, 0ull};
        for (int j = 0; j < Tt - 1; j += 2) {
            u64 v0 = *(const u64*)&Vs[j * 64 + ((myc + 2 * j) & 63)];
            u64 v1 = *(const u64*)&Vs[(j + 1) * 64 + ((myc + 2 * j + 2) & 63)];
            float4 pa = *(const float4*)&Pg[j * 4];
            float4 pb = *(const float4*)&Pg[j * 4 + 4];
            ffma2(a[0], pk2(pa.x, pa.x), v0); ffma2(a[0], pk2(pb.x, pb.x), v1);
            ffma2(a[1], pk2(pa.y, pa.y), v0); ffma2(a[1], pk2(pb.y, pb.y), v1);
            ffma2(a[2], pk2(pa.z, pa.z), v0); ffma2(a[2], pk2(pb.z, pb.z), v1);
            ffma2(a[3], pk2(pa.w, pa.w), v0); ffma2(a[3], pk2(pb.w, pb.w), v1);
        }
        {
            int j = Tt - 1;
            u64 v0 = *(const u64*)&Vs[j * 64 + ((myc + 2 * j) & 63)];
            float4 pa = *(const float4*)&Pg[j * 4];
            ffma2(a[0], pk2(pa.x, pa.x), v0);
            ffma2(a[1], pk2(pa.y, pa.y), v0);
            ffma2(a[2], pk2(pa.z, pa.z), v0);
            ffma2(a[3], pk2(pa.w, pa.w), v0);
        }

#pragma unroll
        for (int s = 0; s < 4; s++) {
            float2 o = upk2(a[s]);
            o.x *= iv[s]; o.y *= iv[s];
            __nv_bfloat16 hx = __float2bfloat16_rn(o.x);
            __nv_bfloat16 hy = __float2bfloat16_rn(o.y);
            __nv_bfloat16 mx2 = __float2bfloat16_rn(o.x - __bfloat162float(hx));
            __nv_bfloat16 my2 = __float2bfloat16_rn(o.y - __bfloat162float(hy));
            const int r = b * Tt + rs[s];
            const int rb = r >> 7, rl = r & 127;
            __nv_bfloat16* t = (__nv_bfloat16*)(ct + ((size_t)rb * NCH + chk) * TILE_U4)
                             + rl * 40 + koff;
            *(__nv_bfloat162*)(t)      = __nv_bfloat162{hx, hy};
            *(__nv_bfloat162*)(t + 16) = __nv_bfloat162{mx2, my2};
        }
        __syncwarp();
    }
}

// ---------------------------------------------------------------------------
extern "C" void kernel_launch(void* const* d_in, const int* in_sizes, int n_in,
                              void* d_out, int out_size)
{
    const float* x  = (const float*)d_in[0];
    const float* Wq = (const float*)d_in[1];
    const float* bq = (const float*)d_in[2];
    const float* Wk = (const float*)d_in[3];
    const float* bk = (const float*)d_in[4];
    const float* Wv = (const float*)d_in[5];
    const float* bv = (const float*)d_in[6];
    const float* Wo = (const float*)d_in[7];
    const float* bo = (const float*)d_in[8];
    float* out = (float*)d_out;

    float *q, *k, *v;
    uint4 *at, *ct, *wt;
    cudaGetSymbolAddress((void**)&q,  g_q);
    cudaGetSymbolAddress((void**)&k,  g_k);
    cudaGetSymbolAddress((void**)&v,  g_v);
    cudaGetSymbolAddress((void**)&at, g_at);
    cudaGetSymbolAddress((void**)&ct, g_ct);
    cudaGetSymbolAddress((void**)&wt, g_wt);

    cudaFuncSetAttribute(bf16_gemm4_kernel,
                         cudaFuncAttributeMaxDynamicSharedMemorySize, GEMM_SMEM_BF);
    cudaFuncSetAttribute(attn3_kernel,
                         cudaFuncAttributeMaxDynamicSharedMemorySize, ATTN_SMEM);

    // limb-tile prep
    prep_a_kernel<<<dim3(NMB, NCH), 128>>>(x, at);
    prep_w_kernel<<<dim3(6, NCH, 2), 128>>>(Wv, Wo, wt);

    // Q, K: exact fp32 FFMA2 (floor-sensitive path)
    dim3 gqk(Dd / 128, NMB, 2);
    qk_kernel<<<gqk, 256>>>(x, Wq, Wk, bq, bk, q, k);

    // V: bf16 tiled GEMM (smooth path)
    dim3 gbf(6, NMB);
    bf16_gemm4_kernel<<<gbf, 128, GEMM_SMEM_BF>>>(at, wt, bv, v, 0);

    // attention -> ctx limb tiles
    attn3_kernel<<<Bc * Hh, 32 * NW, ATTN_SMEM>>>(q, k, v, ct);

    // O: bf16 tiled GEMM
    bf16_gemm4_kernel<<<gbf, 128, GEMM_SMEM_BF>>>(ct, wt + (size_t)6 * NCH * TILE_U4,
                                                  bo, out, 1);
}